// round 9
// baseline (speedup 1.0000x reference)
#include <cuda_runtime.h>
#include <cuda_bf16.h>

#define NTOT 524288
#define DIM  128
#define S    128
#define G    (NTOT / S)
#define MARGIN   2.0f
#define K_MARGIN 0.02f
#define EPS      1e-6f

// Per-group scratch + completion counter (static device allocation — allowed).
__device__ float g_loss[G];
__device__ float g_sumb[G];
__device__ float g_sump[G];
__device__ int   g_cntb[G];
__device__ int   g_done = 0;   // reset by last CTA each launch -> replay-safe

// ---------------------------------------------------------------------------
// Kernel 1: d[i] = 1 - dot(z_r[i], z_v[i]).  One warp per row, float4 loads.
// EXACT config that measured 85.3% DRAM / 6.76 TB/s in round 1 (16 regs).
// ---------------------------------------------------------------------------
__global__ void __launch_bounds__(256) dot_kernel(
    const float4* __restrict__ zr, const float4* __restrict__ zv,
    float* __restrict__ dout)
{
    int gw   = (blockIdx.x * blockDim.x + threadIdx.x) >> 5;   // row id
    int lane = threadIdx.x & 31;
    size_t off = (size_t)gw * 32 + lane;                       // 32 float4 per row
    float4 a = zr[off];
    float4 b = zv[off];
    float s = a.x * b.x + a.y * b.y + a.z * b.z + a.w * b.w;
    #pragma unroll
    for (int o = 16; o; o >>= 1) s += __shfl_xor_sync(0xffffffffu, s, o);
    if (lane == 0) dout[gw] = 1.0f - s;
}

// ---------------------------------------------------------------------------
// Batched block-wide sum over 256 threads (8 warps). All threads get results.
// ---------------------------------------------------------------------------
template<int K>
__device__ __forceinline__ void blockSumK(float* v, float (*red)[8])
{
    #pragma unroll
    for (int k = 0; k < K; k++)
        #pragma unroll
        for (int o = 16; o; o >>= 1)
            v[k] += __shfl_xor_sync(0xffffffffu, v[k], o);
    int w = threadIdx.x >> 5;
    if ((threadIdx.x & 31) == 0)
        #pragma unroll
        for (int k = 0; k < K; k++) red[k][w] = v[k];
    __syncthreads();
    #pragma unroll
    for (int k = 0; k < K; k++)
        v[k] = (red[k][0] + red[k][1]) + (red[k][2] + red[k][3])
             + (red[k][4] + red[k][5]) + (red[k][6] + red[k][7]);
    __syncthreads();
}

// ---------------------------------------------------------------------------
// Kernel 2: one CTA (256 threads) per group; d from hot L2.
//  - single-pass moments (8-way reduction) -> label sums + corr_loss
//  - stable rank via __match_any_sync + per-warp histograms (no O(S) scan)
//  - parallel shuffle-scan prefix over 100 bins
//  - neigh_viol + rank_loss (one 3-way reduction)
//  - last CTA: deterministic double finalize -> out[0], out[1]
// ---------------------------------------------------------------------------
__global__ void __launch_bounds__(256) group_kernel(
    const int* __restrict__ var_lens, const int* __restrict__ labels,
    float* __restrict__ out)
{
    __shared__ int   whist[4][100];  // per-warp histogram (warps 0-3 hold data)
    __shared__ float sds[S];         // d sorted by v (stable)
    __shared__ int   se[S];          // tie-run end (exclusive) at sorted pos
    __shared__ int   P[101];         // exclusive bin prefix; P[100] = S
    __shared__ float red[8][8];
    __shared__ int   wsum[4];        // warp scan partials
    __shared__ int   isLast;

    const int g    = blockIdx.x;
    const int tid  = threadIdx.x;
    const int w    = tid >> 5;
    const int lane = tid & 31;
    const float* dvec = out + 2;

    // zero per-warp histograms (400 ints)
    if (tid < 200) { ((int*)whist)[tid] = 0; ((int*)whist)[tid + 200] = 0; }

    const bool act = tid < S;
    int   v  = 0, lb = -1;
    float di = 0.0f;
    if (act) {
        int idx = g * S + tid;
        di = dvec[idx];                 // L2-hot (written by dot_kernel)
        v  = min(max(var_lens[idx], 0), 99);
        lb = labels[idx];
    }
    __syncthreads();   // whist zeroed before leader writes

    // ---- stable rank within warp via match; leaders publish counts ----
    int rank_in_warp = 0;
    if (act) {
        unsigned m  = __match_any_sync(0xffffffffu, v);
        unsigned lt = m & ((1u << lane) - 1u);
        rank_in_warp = __popc(lt);
        if (lt == 0) whist[w][v] = __popc(m);   // one writer per (warp, bin)
    }

    // ---- single-pass moments: 8 sums, one barrier pass ----
    float vf = act ? (float)v : 0.0f;
    float p1[8] = { lb == 0 ? di : 0.0f, lb == 1 ? di : 0.0f,
                    lb == 0 ? 1.0f : 0.0f,
                    vf, act ? di : 0.0f,
                    vf * vf, di * di, vf * di };
    blockSumK<8>(p1, red);             // includes the __syncthreads for whist
    float sb = p1[0], sp = p1[1], cb = p1[2];
    float sumv = p1[3], sumd = p1[4];
    float mv = sumv * (1.0f / S), md = sumd * (1.0f / S);
    float ssv = fmaxf(p1[5] - sumv * mv, 0.0f);   // Σ(v-mv)²
    float ssd = fmaxf(p1[6] - sumd * md, 0.0f);   // Σ(d-md)²
    float cov = p1[7] - sumv * md;                // Σ(v-mv)(d-md)
    float vs = sqrtf(ssv * (1.0f / (S - 1)));
    float ds = sqrtf(ssd * (1.0f / (S - 1)));
    float ia = 1.0f / (vs + EPS), ib = 1.0f / (ds + EPS);
    float corr = (ssv * ia * ia + ssd * ib * ib - 2.0f * cov * ia * ib) * (1.0f / S);
    if (!(vs > 0.0f && ds > 0.0f)) corr = 0.0f;

    // ---- parallel exclusive prefix over 100 bins (threads 0..127) ----
    int c = 0;
    if (tid < 100)
        c = whist[0][tid] + whist[1][tid] + whist[2][tid] + whist[3][tid];
    int x = c;
    #pragma unroll
    for (int o = 1; o < 32; o <<= 1) {
        int y = __shfl_up_sync(0xffffffffu, x, o);
        if (lane >= o) x += y;
    }
    if (tid < 128 && lane == 31) wsum[w] = x;
    __syncthreads();
    if (tid <= 100) {
        int off = 0;
        #pragma unroll
        for (int q = 0; q < 3; q++) off += (w > q) ? wsum[q] : 0;
        P[tid] = x - c + off;          // exclusive; P[100] = 128
    }
    __syncthreads();

    // ---- stable scatter ----
    if (act) {
        int rk = rank_in_warp;
        if (w > 0) rk += whist[0][v];
        if (w > 1) rk += whist[1][v];
        if (w > 2) rk += whist[2][v];
        int pos = P[v] + rk;
        sds[pos] = di;
        se[pos]  = P[v + 1];           // end (exclusive) of this tie run
    }
    __syncthreads();

    // ---- neigh_viol + rank_loss (3 sums, one barrier pass) ----
    float nv = (tid < S - 1) ? fmaxf(sds[tid] - sds[tid + 1] + K_MARGIN, 0.0f) : 0.0f;
    const int   i   = tid & (S - 1);
    const int   h   = tid >> 7;
    const int   e   = se[i];
    const float ddi = sds[i] + K_MARGIN;
    float viol = 0.0f;
    for (int j = e + h; j < S; j += 2)
        viol += fmaxf(ddi - sds[j], 0.0f);
    float p4[3] = { nv, h == 0 ? (float)(S - e) : 0.0f, viol };
    blockSumK<3>(p4, red);
    float neigh = p4[0] * (1.0f / (S - 1));
    float rankl = (p4[1] > 0.0f) ? p4[2] / p4[1] : 0.0f;

    if (tid == 0) {
        g_loss[g] = corr + neigh + rankl;
        g_sumb[g] = sb;
        g_sump[g] = sp;
        g_cntb[g] = (int)cb;
        __threadfence();
        int old = atomicAdd(&g_done, 1);
        isLast = (old == G - 1);
    }
    __syncthreads();

    // ---------------- last CTA finalizes ----------------
    if (isLast) {
        __shared__ double shL[256], shB[256], shP[256];
        __shared__ long long shC[256];

        double aL = 0.0, aB = 0.0, aP = 0.0;
        long long cB = 0;
        #pragma unroll 4
        for (int q = tid; q < G; q += 256) {
            aL += (double)g_loss[q];
            aB += (double)g_sumb[q];
            aP += (double)g_sump[q];
            cB += (long long)g_cntb[q];
        }
        shL[tid] = aL; shB[tid] = aB; shP[tid] = aP; shC[tid] = cB;
        __syncthreads();
        #pragma unroll
        for (int s = 128; s > 0; s >>= 1) {
            if (tid < s) {
                shL[tid] += shL[tid + s];
                shB[tid] += shB[tid + s];
                shP[tid] += shP[tid + s];
                shC[tid] += shC[tid + s];
            }
            __syncthreads();
        }
        if (tid == 0) {
            long long nb = shC[0];
            long long np = (long long)NTOT - nb;
            double mb = shB[0] / (double)(nb > 1 ? nb : 1);
            double mp = shP[0] / (double)(np > 1 ? np : 1);
            double lcdd = (nb > 0 && np > 0) ? (MARGIN + mb - mp) : 0.0;
            if (lcdd < 0.0) lcdd = 0.0;
            out[0] = (float)lcdd;
            out[1] = (float)(shL[0] / (double)G);
            g_done = 0;            // reset for next graph replay
        }
    }
}

// ---------------------------------------------------------------------------
extern "C" void kernel_launch(void* const* d_in, const int* in_sizes, int n_in,
                              void* d_out, int out_size)
{
    const float* zr       = (const float*)d_in[0];
    const float* zv       = (const float*)d_in[1];
    const int*   labels   = (const int*)d_in[2];
    // d_in[3] = groups (== i / S by construction, unused)
    const int*   var_lens = (const int*)d_in[4];
    float* out = (float*)d_out;

    dot_kernel<<<NTOT / 8, 256>>>((const float4*)zr, (const float4*)zv, out + 2);
    group_kernel<<<G, 256>>>(var_lens, labels, out);
}